// round 12
// baseline (speedup 1.0000x reference)
#include <cuda_runtime.h>
#include <cuda_bf16.h>
#include <cuda_pipeline.h>
#include <cstdint>

#define N_SEQ   32768
#define D_MODEL 1024
#define KCTX    8
#define LCTX    9
#define HEADS   16
#define DHEAD   64
#define MROWS_C (N_SEQ * LCTX)   /* 294912 */

// ---------------- scratch (static device globals; no allocation) ----------------
__device__ __nv_bfloat16 g_qn_h[(size_t)N_SEQ   * D_MODEL];
__device__ __nv_bfloat16 g_cn_h[(size_t)MROWS_C * D_MODEL];
__device__ __nv_bfloat16 g_o_h [(size_t)N_SEQ   * D_MODEL];
__device__ __nv_bfloat16 g_q_h [(size_t)N_SEQ   * D_MODEL];   // bf16 q
__device__ __nv_bfloat16 g_k_h [(size_t)MROWS_C * D_MODEL];   // bf16 k
__device__ __nv_bfloat16 g_v_h [(size_t)MROWS_C * D_MODEL];   // bf16 v
// transposed bf16 weights: Wt[n][k] = W[k][n]  (K-major, same layout as A)
__device__ __nv_bfloat16 g_wqt[(size_t)D_MODEL * D_MODEL];
__device__ __nv_bfloat16 g_wkt[(size_t)D_MODEL * D_MODEL];
__device__ __nv_bfloat16 g_wvt[(size_t)D_MODEL * D_MODEL];
__device__ __nv_bfloat16 g_wot[(size_t)D_MODEL * D_MODEL];

// ---------------- PTX primitives ----------------
__device__ __forceinline__ uint32_t smem_u32(const void* p) {
    uint32_t a;
    asm("{ .reg .u64 t; cvta.to.shared.u64 t, %1; cvt.u32.u64 %0, t; }" : "=r"(a) : "l"(p));
    return a;
}

__device__ __forceinline__ void ldsm_x4(uint32_t* r, uint32_t addr) {
    asm volatile("ldmatrix.sync.aligned.m8n8.x4.shared.b16 {%0,%1,%2,%3}, [%4];"
                 : "=r"(r[0]), "=r"(r[1]), "=r"(r[2]), "=r"(r[3]) : "r"(addr));
}

__device__ __forceinline__ void mma16816(float* c, const uint32_t* a,
                                         uint32_t b0, uint32_t b1) {
    asm volatile(
        "mma.sync.aligned.m16n8k16.row.col.f32.bf16.bf16.f32 "
        "{%0,%1,%2,%3}, {%4,%5,%6,%7}, {%8,%9}, {%0,%1,%2,%3};"
        : "+f"(c[0]), "+f"(c[1]), "+f"(c[2]), "+f"(c[3])
        : "r"(a[0]), "r"(a[1]), "r"(a[2]), "r"(a[3]), "r"(b0), "r"(b1));
}

// ---------------- weight convert + transpose: Wt[n][k] = bf16(W[k][n]) ---------
template<int W>
__global__ void __launch_bounds__(256) cvtT_kernel(const float* __restrict__ src)
{
    __nv_bfloat16* dst = (W == 0) ? g_wqt : (W == 1) ? g_wkt : (W == 2) ? g_wvt : g_wot;
    __shared__ float t[32][33];
    int tx = threadIdx.x & 31, ty = threadIdx.x >> 5;  // 32 x 8
    int n0 = blockIdx.x * 32, k0 = blockIdx.y * 32;
#pragma unroll
    for (int j = 0; j < 4; j++)
        t[ty + j * 8][tx] = src[(size_t)(k0 + ty + j * 8) * D_MODEL + n0 + tx];
    __syncthreads();
#pragma unroll
    for (int j = 0; j < 4; j++) {
        int n = ty + j * 8;
        dst[(size_t)(n0 + n) * D_MODEL + k0 + tx] = __float2bfloat16(t[tx][n]);
    }
}

// ---------------- LayerNorm ----------------
// warps < N_SEQ: read feat row once, write BOTH g_qn_h and g_cn_h[n*9].
// warps >= N_SEQ: context rows l = 1..8 -> g_cn_h[n*9 + l].
__global__ void __launch_bounds__(256) ln_kernel(
    const float* __restrict__ feat, const float* __restrict__ ctx,
    const float* __restrict__ qg, const float* __restrict__ qb,
    const float* __restrict__ cg, const float* __restrict__ cb)
{
    int warp = (blockIdx.x * blockDim.x + threadIdx.x) >> 5;
    int lane = threadIdx.x & 31;

    bool dual = (warp < N_SEQ);
    const float* src;
    __nv_bfloat16* dst1;
    const float* gp1; const float* bp1;
    __nv_bfloat16* dst2 = nullptr;
    if (dual) {
        src = feat + (size_t)warp * D_MODEL;
        gp1 = qg; bp1 = qb;
        dst1 = g_qn_h + (size_t)warp * D_MODEL;
        dst2 = g_cn_h + (size_t)(warp * LCTX) * D_MODEL;
    } else {
        int r = warp - N_SEQ;
        int n = r >> 3, l = 1 + (r & 7);
        src = ctx + ((size_t)n * KCTX + (l - 1)) * D_MODEL;
        gp1 = cg; bp1 = cb;
        dst1 = g_cn_h + (size_t)(n * LCTX + l) * D_MODEL;
    }

    float4 x[8];
    float s = 0.f, ss = 0.f;
#pragma unroll
    for (int j = 0; j < 8; j++) {
        x[j] = reinterpret_cast<const float4*>(src)[j * 32 + lane];
        s  += x[j].x + x[j].y + x[j].z + x[j].w;
        ss += x[j].x * x[j].x + x[j].y * x[j].y + x[j].z * x[j].z + x[j].w * x[j].w;
    }
#pragma unroll
    for (int o = 16; o; o >>= 1) {
        s  += __shfl_xor_sync(0xFFFFFFFFu, s,  o);
        ss += __shfl_xor_sync(0xFFFFFFFFu, ss, o);
    }
    float mean = s * (1.f / 1024.f);
    float var  = ss * (1.f / 1024.f) - mean * mean;
    float rstd = rsqrtf(var + 1e-5f);

#pragma unroll
    for (int j = 0; j < 8; j++) {
        float4 g4 = reinterpret_cast<const float4*>(gp1)[j * 32 + lane];
        float4 b4 = reinterpret_cast<const float4*>(bp1)[j * 32 + lane];
        float nx = (x[j].x - mean) * rstd;
        float ny = (x[j].y - mean) * rstd;
        float nz = (x[j].z - mean) * rstd;
        float nw = (x[j].w - mean) * rstd;
        __nv_bfloat162 p0 = __floats2bfloat162_rn(nx * g4.x + b4.x, ny * g4.y + b4.y);
        __nv_bfloat162 p1 = __floats2bfloat162_rn(nz * g4.z + b4.z, nw * g4.w + b4.w);
        uint2 u;
        u.x = *reinterpret_cast<unsigned int*>(&p0);
        u.y = *reinterpret_cast<unsigned int*>(&p1);
        reinterpret_cast<uint2*>(dst1)[j * 32 + lane] = u;
        if (dual) {
            float4 c4 = reinterpret_cast<const float4*>(cg)[j * 32 + lane];
            float4 d4 = reinterpret_cast<const float4*>(cb)[j * 32 + lane];
            __nv_bfloat162 q0 = __floats2bfloat162_rn(nx * c4.x + d4.x, ny * c4.y + d4.y);
            __nv_bfloat162 q1 = __floats2bfloat162_rn(nz * c4.z + d4.z, nw * c4.w + d4.w);
            uint2 v;
            v.x = *reinterpret_cast<unsigned int*>(&q0);
            v.y = *reinterpret_cast<unsigned int*>(&q1);
            reinterpret_cast<uint2*>(dst2)[j * 32 + lane] = v;
        }
    }
}

// ---------------- raw-PTX bf16 GEMM core (R9/R11-proven shape) -------------------
// BM=BN=128, BK=64, 4 warps (2x2), warp tile 64x64, 3-stage cp.async, 2 CTAs/SM.
constexpr int BK = 64;
constexpr int ROWPAD = BK + 8;                 // 72 bf16 = 144B row pitch
constexpr int A_BYTES = 128 * ROWPAD * 2;      // 18432
constexpr int STAGE_BYTES = 256 * ROWPAD * 2;  // 36864 B per stage
constexpr int GEMM_STAGES = 3;
constexpr int GEMM_SMEM_DYN = GEMM_STAGES * STAGE_BYTES;  // 110592
constexpr int NT_K = D_MODEL / BK;             // 16
constexpr int EPIPITCH = 68;

// Shared GEMM body. FUSED=0: bf16 store to Ch. FUSED=1: f32 out = acc+bout+feat.
template<int FUSED>
__device__ __forceinline__ void gemm_body(
    const __nv_bfloat16* __restrict__ A, const __nv_bfloat16* __restrict__ Bt,
    __nv_bfloat16* __restrict__ Ch,
    size_t bm, int bn,
    const float* __restrict__ feat, const float* __restrict__ bout,
    float* __restrict__ outp, char* sm0)
{
    uint32_t sm0_u = smem_u32(sm0);
    int tid = threadIdx.x;
    int wid = tid >> 5, lane = tid & 31;

    int wm = (wid >> 1) * 64;
    int wn = (wid & 1) * 64;

    float acc[4][8][4];
#pragma unroll
    for (int i = 0; i < 4; i++)
#pragma unroll
        for (int j = 0; j < 8; j++)
#pragma unroll
            for (int e = 0; e < 4; e++) acc[i][j][e] = 0.f;

    uint32_t offA[4], offB[4];
#pragma unroll
    for (int mi = 0; mi < 4; mi++)
        offA[mi] = (uint32_t)(((wm + mi * 16 + (lane & 15)) * ROWPAD + ((lane >> 4) << 3)) * 2);
#pragma unroll
    for (int pi = 0; pi < 4; pi++)
        offB[pi] = (uint32_t)(A_BYTES +
                   ((wn + pi * 16 + (lane & 7) + ((lane >> 4) << 3)) * ROWPAD +
                    (((lane >> 3) & 1) << 3)) * 2);

    auto load_stage = [&](int kt) {
        char* base = sm0 + (kt % GEMM_STAGES) * STAGE_BYTES;
#pragma unroll
        for (int i = 0; i < 8; i++) {
            int id = tid + i * 128;
            int row = id >> 3, c = id & 7;
            __pipeline_memcpy_async(base + row * 144 + c * 16,
                                    A + (bm + row) * D_MODEL + kt * BK + c * 8, 16);
        }
#pragma unroll
        for (int i = 0; i < 8; i++) {
            int id = tid + i * 128;
            int row = id >> 3, c = id & 7;
            __pipeline_memcpy_async(base + A_BYTES + row * 144 + c * 16,
                                    Bt + (size_t)(bn + row) * D_MODEL + kt * BK + c * 8, 16);
        }
    };

    load_stage(0); __pipeline_commit();
    load_stage(1); __pipeline_commit();

    uint32_t a[2][4][4], b[2][4][4];

    for (int kt = 0; kt < NT_K; kt++) {
        __pipeline_wait_prior(1);
        __syncthreads();

        if (kt + 2 < NT_K) load_stage(kt + 2);
        __pipeline_commit();

        uint32_t st = sm0_u + (uint32_t)((kt % GEMM_STAGES) * STAGE_BYTES);

#pragma unroll
        for (int mi = 0; mi < 4; mi++) ldsm_x4(a[0][mi], st + offA[mi]);
#pragma unroll
        for (int pi = 0; pi < 4; pi++) ldsm_x4(b[0][pi], st + offB[pi]);

#pragma unroll
        for (int cs = 0; cs < 4; cs++) {
            int cur = cs & 1, nxt = cur ^ 1;
            if (cs < 3) {
                uint32_t koff = (uint32_t)((cs + 1) * 32);
#pragma unroll
                for (int mi = 0; mi < 4; mi++) ldsm_x4(a[nxt][mi], st + offA[mi] + koff);
#pragma unroll
                for (int pi = 0; pi < 4; pi++) ldsm_x4(b[nxt][pi], st + offB[pi] + koff);
            }
#pragma unroll
            for (int mi = 0; mi < 4; mi++)
#pragma unroll
                for (int ni = 0; ni < 8; ni++) {
                    int pi = ni >> 1, sel = (ni & 1) * 2;
                    mma16816(acc[mi][ni], a[cur][mi], b[cur][pi][sel], b[cur][pi][sel + 1]);
                }
        }
    }

    // epilogue via per-warp smem stage (16 x 64, pitch 68)
    __syncthreads();
    float* stage = reinterpret_cast<float*>(sm0) + wid * 1088;

    int srow = lane >> 2;
    int scol0 = (lane & 3) * 2;

#pragma unroll
    for (int mi = 0; mi < 4; mi++) {
#pragma unroll
        for (int ni = 0; ni < 8; ni++) {
            int col = ni * 8 + scol0;
            stage[srow * EPIPITCH + col]           = acc[mi][ni][0];
            stage[srow * EPIPITCH + col + 1]       = acc[mi][ni][1];
            stage[(srow + 8) * EPIPITCH + col]     = acc[mi][ni][2];
            stage[(srow + 8) * EPIPITCH + col + 1] = acc[mi][ni][3];
        }
        __syncwarp();
        size_t grow = bm + wm + mi * 16;

        if (FUSED == 0) {
#pragma unroll
            for (int u = 0; u < 16; u++) {
                int e = lane + u * 32;
                int r = e >> 5, c2 = e & 31;
                float2 f2 = *reinterpret_cast<const float2*>(stage + r * EPIPITCH + c2 * 2);
                __nv_bfloat162 h2 = __floats2bfloat162_rn(f2.x, f2.y);
                *reinterpret_cast<__nv_bfloat162*>(
                    Ch + (grow + r) * D_MODEL + bn + wn + c2 * 2) = h2;
            }
        } else {
#pragma unroll
            for (int u = 0; u < 16; u++) {
                int e = lane + u * 32;
                int r = e >> 5, c2 = e & 31;
                int gc = bn + wn + c2 * 2;
                float2 f2 = *reinterpret_cast<const float2*>(stage + r * EPIPITCH + c2 * 2);
                float2 b2 = *reinterpret_cast<const float2*>(bout + gc);
                float2 ff = *reinterpret_cast<const float2*>(feat + (grow + r) * D_MODEL + gc);
                float2 o2;
                o2.x = f2.x + b2.x + ff.x;
                o2.y = f2.y + b2.y + ff.y;
                *reinterpret_cast<float2*>(outp + (grow + r) * D_MODEL + gc) = o2;
            }
        }
        __syncwarp();
    }
}

// Single merged launch for ALL THREE projections (q, k, v).
// grid = (16, 2432):
//   y < 2304          : K/V rows. x<8 -> cn@Wk->k, x>=8 -> cn@Wv->v. bn=(x&7)*128, bm=y*128.
//   y >= 2304 (128 ys): q tiles. idx=(y-2304)*16+x in [0,2048): bm=(idx>>3)*128, bn=(idx&7)*128.
__global__ void __launch_bounds__(128, 2) gemm_qkv_kernel()
{
    extern __shared__ __align__(16) char sm0[];

    const __nv_bfloat16* A;
    const __nv_bfloat16* Bt;
    __nv_bfloat16* Ch;
    size_t bm;
    int bn;

    if (blockIdx.y < 2304) {
        A = g_cn_h;
        bool isK = (blockIdx.x < 8);
        Bt = isK ? g_wkt : g_wvt;
        Ch = isK ? g_k_h : g_v_h;
        bn = (blockIdx.x & 7) * 128;
        bm = (size_t)blockIdx.y * 128;
    } else {
        int idx = (blockIdx.y - 2304) * 16 + blockIdx.x;   // 0..2047
        A  = g_qn_h;
        Bt = g_wqt;
        Ch = g_q_h;
        bm = (size_t)(idx >> 3) * 128;
        bn = (idx & 7) * 128;
    }

    gemm_body<0>(A, Bt, Ch, bm, bn, nullptr, nullptr, nullptr, sm0);
}

// Output projection: o@Wout -> out (fused +bout+feat), grid = (8, 256)
__global__ void __launch_bounds__(128, 2) gemm_out_kernel(
    const float* __restrict__ feat, const float* __restrict__ bout,
    float* __restrict__ outp)
{
    extern __shared__ __align__(16) char sm0[];
    gemm_body<1>(g_o_h, g_wot, nullptr,
                 (size_t)blockIdx.y * 128, blockIdx.x * 128,
                 feat, bout, outp, sm0);
}

// ---------------- attention: one warp per (n, h), L = 9, all bf16 ---------------
__global__ void __launch_bounds__(256) attn_kernel()
{
    int warp = (blockIdx.x * blockDim.x + threadIdx.x) >> 5;
    int lane = threadIdx.x & 31;
    int n = warp >> 4;
    int h = warp & 15;

    size_t qoff = (size_t)n * D_MODEL + h * DHEAD + lane * 2;
    __nv_bfloat162 q2 = *reinterpret_cast<const __nv_bfloat162*>(g_q_h + qoff);
    float2 q = __bfloat1622float2(q2);

    float sc[LCTX];
#pragma unroll
    for (int l = 0; l < LCTX; l++) {
        size_t koff = (size_t)(n * LCTX + l) * D_MODEL + h * DHEAD + lane * 2;
        __nv_bfloat162 k2 = *reinterpret_cast<const __nv_bfloat162*>(g_k_h + koff);
        float2 kk = __bfloat1622float2(k2);
        float p = q.x * kk.x + q.y * kk.y;
#pragma unroll
        for (int o = 16; o; o >>= 1) p += __shfl_xor_sync(0xFFFFFFFFu, p, o);
        sc[l] = p * 0.125f;
    }
    float m = sc[0];
#pragma unroll
    for (int l = 1; l < LCTX; l++) m = fmaxf(m, sc[l]);
    float sum = 0.f;
#pragma unroll
    for (int l = 0; l < LCTX; l++) { sc[l] = __expf(sc[l] - m); sum += sc[l]; }
    float inv = 1.f / sum;

    float ox = 0.f, oy = 0.f;
#pragma unroll
    for (int l = 0; l < LCTX; l++) {
        size_t voff = (size_t)(n * LCTX + l) * D_MODEL + h * DHEAD + lane * 2;
        __nv_bfloat162 v2 = *reinterpret_cast<const __nv_bfloat162*>(g_v_h + voff);
        float2 vv = __bfloat1622float2(v2);
        float p = sc[l] * inv;
        ox = fmaf(p, vv.x, ox);
        oy = fmaf(p, vv.y, oy);
    }
    __nv_bfloat162 o2 = __floats2bfloat162_rn(ox, oy);
    *reinterpret_cast<__nv_bfloat162*>(g_o_h + qoff) = o2;
}

// ---------------- launch ----------------
extern "C" void kernel_launch(void* const* d_in, const int* in_sizes, int n_in,
                              void* d_out, int out_size)
{
    const float* feat = (const float*)d_in[0];
    const float* ctx  = (const float*)d_in[1];
    const float* qg   = (const float*)d_in[2];
    const float* qb   = (const float*)d_in[3];
    const float* cg   = (const float*)d_in[4];
    const float* cb   = (const float*)d_in[5];
    const float* Wq   = (const float*)d_in[6];
    const float* Wk   = (const float*)d_in[7];
    const float* Wv   = (const float*)d_in[8];
    const float* Wout = (const float*)d_in[9];
    const float* bout = (const float*)d_in[10];
    float* out = (float*)d_out;

    cudaFuncSetAttribute(gemm_qkv_kernel, cudaFuncAttributeMaxDynamicSharedMemorySize, GEMM_SMEM_DYN);
    cudaFuncSetAttribute(gemm_out_kernel, cudaFuncAttributeMaxDynamicSharedMemorySize, GEMM_SMEM_DYN);

    cvtT_kernel<0><<<dim3(32, 32), 256>>>(Wq);
    cvtT_kernel<1><<<dim3(32, 32), 256>>>(Wk);
    cvtT_kernel<2><<<dim3(32, 32), 256>>>(Wv);
    cvtT_kernel<3><<<dim3(32, 32), 256>>>(Wout);

    // warps: N_SEQ dual-output + N_SEQ*8 context = 294912 warps / 8 per block
    ln_kernel<<<MROWS_C / 8, 256>>>(feat, ctx, qg, qb, cg, cb);

    // one launch for q + k + v projections
    gemm_qkv_kernel<<<dim3(16, 2432), 128, GEMM_SMEM_DYN>>>();

    attn_kernel<<<(N_SEQ * HEADS) / 8, 256>>>();

    gemm_out_kernel<<<dim3(8, N_SEQ / 128), 128, GEMM_SMEM_DYN>>>(feat, bout, out);
}

// round 13
// speedup vs baseline: 1.0797x; 1.0797x over previous
#include <cuda_runtime.h>
#include <cuda_bf16.h>
#include <cuda_pipeline.h>
#include <cstdint>

#define N_SEQ   32768
#define D_MODEL 1024
#define KCTX    8
#define LCTX    9
#define HEADS   16
#define DHEAD   64
#define MROWS_C (N_SEQ * LCTX)   /* 294912 */

// ---------------- scratch (static device globals; no allocation) ----------------
__device__ __nv_bfloat16 g_qn_h[(size_t)N_SEQ   * D_MODEL];
__device__ __nv_bfloat16 g_cn_h[(size_t)MROWS_C * D_MODEL];
__device__ __nv_bfloat16 g_o_h [(size_t)N_SEQ   * D_MODEL];
__device__ __nv_bfloat16 g_q_h [(size_t)N_SEQ   * D_MODEL];   // bf16 q
__device__ __nv_bfloat16 g_k_h [(size_t)MROWS_C * D_MODEL];   // bf16 k
__device__ __nv_bfloat16 g_v_h [(size_t)MROWS_C * D_MODEL];   // bf16 v
// transposed bf16 weights: Wt[n][k] = W[k][n]  (K-major, same layout as A)
__device__ __nv_bfloat16 g_wqt[(size_t)D_MODEL * D_MODEL];
__device__ __nv_bfloat16 g_wkt[(size_t)D_MODEL * D_MODEL];
__device__ __nv_bfloat16 g_wvt[(size_t)D_MODEL * D_MODEL];
__device__ __nv_bfloat16 g_wot[(size_t)D_MODEL * D_MODEL];

// ---------------- PTX primitives ----------------
__device__ __forceinline__ uint32_t smem_u32(const void* p) {
    uint32_t a;
    asm("{ .reg .u64 t; cvta.to.shared.u64 t, %1; cvt.u32.u64 %0, t; }" : "=r"(a) : "l"(p));
    return a;
}

__device__ __forceinline__ void ldsm_x4(uint32_t* r, uint32_t addr) {
    asm volatile("ldmatrix.sync.aligned.m8n8.x4.shared.b16 {%0,%1,%2,%3}, [%4];"
                 : "=r"(r[0]), "=r"(r[1]), "=r"(r[2]), "=r"(r[3]) : "r"(addr));
}

__device__ __forceinline__ void mma16816(float* c, const uint32_t* a,
                                         uint32_t b0, uint32_t b1) {
    asm volatile(
        "mma.sync.aligned.m16n8k16.row.col.f32.bf16.bf16.f32 "
        "{%0,%1,%2,%3}, {%4,%5,%6,%7}, {%8,%9}, {%0,%1,%2,%3};"
        : "+f"(c[0]), "+f"(c[1]), "+f"(c[2]), "+f"(c[3])
        : "r"(a[0]), "r"(a[1]), "r"(a[2]), "r"(a[3]), "r"(b0), "r"(b1));
}

// ---------------- weight convert + transpose: Wt[n][k] = bf16(W[k][n]) ---------
template<int W>
__global__ void __launch_bounds__(256) cvtT_kernel(const float* __restrict__ src)
{
    __nv_bfloat16* dst = (W == 0) ? g_wqt : (W == 1) ? g_wkt : (W == 2) ? g_wvt : g_wot;
    __shared__ float t[32][33];
    int tx = threadIdx.x & 31, ty = threadIdx.x >> 5;  // 32 x 8
    int n0 = blockIdx.x * 32, k0 = blockIdx.y * 32;
#pragma unroll
    for (int j = 0; j < 4; j++)
        t[ty + j * 8][tx] = src[(size_t)(k0 + ty + j * 8) * D_MODEL + n0 + tx];
    __syncthreads();
#pragma unroll
    for (int j = 0; j < 4; j++) {
        int n = ty + j * 8;
        dst[(size_t)(n0 + n) * D_MODEL + k0 + tx] = __float2bfloat16(t[tx][n]);
    }
}

// ---------------- LayerNorm ----------------
// warps < N_SEQ: read feat row once, write BOTH g_qn_h and g_cn_h[n*9].
// warps >= N_SEQ: context rows l = 1..8 -> g_cn_h[n*9 + l].
__global__ void __launch_bounds__(256) ln_kernel(
    const float* __restrict__ feat, const float* __restrict__ ctx,
    const float* __restrict__ qg, const float* __restrict__ qb,
    const float* __restrict__ cg, const float* __restrict__ cb)
{
    int warp = (blockIdx.x * blockDim.x + threadIdx.x) >> 5;
    int lane = threadIdx.x & 31;

    bool dual = (warp < N_SEQ);
    const float* src;
    __nv_bfloat16* dst1;
    const float* gp1; const float* bp1;
    __nv_bfloat16* dst2 = nullptr;
    if (dual) {
        src = feat + (size_t)warp * D_MODEL;
        gp1 = qg; bp1 = qb;
        dst1 = g_qn_h + (size_t)warp * D_MODEL;
        dst2 = g_cn_h + (size_t)(warp * LCTX) * D_MODEL;
    } else {
        int r = warp - N_SEQ;
        int n = r >> 3, l = 1 + (r & 7);
        src = ctx + ((size_t)n * KCTX + (l - 1)) * D_MODEL;
        gp1 = cg; bp1 = cb;
        dst1 = g_cn_h + (size_t)(n * LCTX + l) * D_MODEL;
    }

    float4 x[8];
    float s = 0.f, ss = 0.f;
#pragma unroll
    for (int j = 0; j < 8; j++) {
        x[j] = reinterpret_cast<const float4*>(src)[j * 32 + lane];
        s  += x[j].x + x[j].y + x[j].z + x[j].w;
        ss += x[j].x * x[j].x + x[j].y * x[j].y + x[j].z * x[j].z + x[j].w * x[j].w;
    }
#pragma unroll
    for (int o = 16; o; o >>= 1) {
        s  += __shfl_xor_sync(0xFFFFFFFFu, s,  o);
        ss += __shfl_xor_sync(0xFFFFFFFFu, ss, o);
    }
    float mean = s * (1.f / 1024.f);
    float var  = ss * (1.f / 1024.f) - mean * mean;
    float rstd = rsqrtf(var + 1e-5f);

#pragma unroll
    for (int j = 0; j < 8; j++) {
        float4 g4 = reinterpret_cast<const float4*>(gp1)[j * 32 + lane];
        float4 b4 = reinterpret_cast<const float4*>(bp1)[j * 32 + lane];
        float nx = (x[j].x - mean) * rstd;
        float ny = (x[j].y - mean) * rstd;
        float nz = (x[j].z - mean) * rstd;
        float nw = (x[j].w - mean) * rstd;
        __nv_bfloat162 p0 = __floats2bfloat162_rn(nx * g4.x + b4.x, ny * g4.y + b4.y);
        __nv_bfloat162 p1 = __floats2bfloat162_rn(nz * g4.z + b4.z, nw * g4.w + b4.w);
        uint2 u;
        u.x = *reinterpret_cast<unsigned int*>(&p0);
        u.y = *reinterpret_cast<unsigned int*>(&p1);
        reinterpret_cast<uint2*>(dst1)[j * 32 + lane] = u;
        if (dual) {
            float4 c4 = reinterpret_cast<const float4*>(cg)[j * 32 + lane];
            float4 d4 = reinterpret_cast<const float4*>(cb)[j * 32 + lane];
            __nv_bfloat162 q0 = __floats2bfloat162_rn(nx * c4.x + d4.x, ny * c4.y + d4.y);
            __nv_bfloat162 q1 = __floats2bfloat162_rn(nz * c4.z + d4.z, nw * c4.w + d4.w);
            uint2 v;
            v.x = *reinterpret_cast<unsigned int*>(&q0);
            v.y = *reinterpret_cast<unsigned int*>(&q1);
            reinterpret_cast<uint2*>(dst2)[j * 32 + lane] = v;
        }
    }
}

// ---------------- persistent raw-PTX bf16 GEMM -----------------------------------
// Inner loop identical to R11 (BM=BN=128, BK=64, 4 warps 2x2, 64x64 warp tile,
// 3-stage cp.async, 2 CTAs/SM). Persistent CTAs grid-stride over tiles with a
// CONTINUOUS chunk pipeline: tiles' k-chunks share one 3-buffer rotation, so the
// pipeline never drains at tile boundaries. Epilogue stages into the just-freed
// buffer (not targeted by in-flight loads).
constexpr int BK = 64;
constexpr int ROWPAD = BK + 8;                 // 72 bf16 = 144B row pitch
constexpr int A_BYTES = 128 * ROWPAD * 2;      // 18432
constexpr int STAGE_BYTES = 256 * ROWPAD * 2;  // 36864 B per stage
constexpr int GEMM_STAGES = 3;
constexpr int GEMM_SMEM_DYN = GEMM_STAGES * STAGE_BYTES;  // 110592
constexpr int NT_K = D_MODEL / BK;             // 16
constexpr int EPIPITCH = 68;

constexpr int QKV_TILES = (MROWS_C / 128) * 16 + (N_SEQ / 128) * 8;  // 36864 + 2048
constexpr int OUT_TILES = (N_SEQ / 128) * 8;                          // 2048

// WHICH 0: qkv projections (bf16 out).  WHICH 1: out-projection (fused f32 out).
template<int WHICH>
__global__ void __launch_bounds__(128, 2) gemm_pers(
    int n_tiles,
    const float* __restrict__ feat, const float* __restrict__ bout,
    float* __restrict__ outp)
{
    extern __shared__ __align__(16) char sm0[];
    uint32_t sm0_u = smem_u32(sm0);

    int tid = threadIdx.x;
    int wid = tid >> 5, lane = tid & 31;
    int wm = (wid >> 1) * 64;
    int wn = (wid & 1) * 64;
    int stride = gridDim.x;

    uint32_t offA[4], offB[4];
#pragma unroll
    for (int mi = 0; mi < 4; mi++)
        offA[mi] = (uint32_t)(((wm + mi * 16 + (lane & 15)) * ROWPAD + ((lane >> 4) << 3)) * 2);
#pragma unroll
    for (int pi = 0; pi < 4; pi++)
        offB[pi] = (uint32_t)(A_BYTES +
                   ((wn + pi * 16 + (lane & 7) + ((lane >> 4) << 3)) * ROWPAD +
                    (((lane >> 3) & 1) << 3)) * 2);

    auto decode = [&](int t, const __nv_bfloat16*& A, const __nv_bfloat16*& B,
                      __nv_bfloat16*& C, size_t& bm, int& bn) {
        if (WHICH == 0) {
            if (t < (MROWS_C / 128) * 16) {
                int x = t & 15;
                A = g_cn_h;
                bool isK = (x < 8);
                B = isK ? g_wkt : g_wvt;
                C = isK ? g_k_h : g_v_h;
                bn = (x & 7) * 128;
                bm = (size_t)(t >> 4) * 128;
            } else {
                int idx = t - (MROWS_C / 128) * 16;
                A = g_qn_h; B = g_wqt; C = g_q_h;
                bm = (size_t)(idx >> 3) * 128;
                bn = (idx & 7) * 128;
            }
        } else {
            A = g_o_h; B = g_wot; C = nullptr;
            bm = (size_t)(t >> 3) * 128;
            bn = (t & 7) * 128;
        }
    };

    auto load_chunk = [&](const __nv_bfloat16* A, const __nv_bfloat16* B,
                          size_t bm, int bn, int kt, int buf) {
        char* base = sm0 + buf * STAGE_BYTES;
#pragma unroll
        for (int i = 0; i < 8; i++) {
            int id = tid + i * 128;
            int row = id >> 3, c = id & 7;
            __pipeline_memcpy_async(base + row * 144 + c * 16,
                                    A + (bm + row) * D_MODEL + kt * BK + c * 8, 16);
        }
#pragma unroll
        for (int i = 0; i < 8; i++) {
            int id = tid + i * 128;
            int row = id >> 3, c = id & 7;
            __pipeline_memcpy_async(base + A_BYTES + row * 144 + c * 16,
                                    B + (size_t)(bn + row) * D_MODEL + kt * BK + c * 8, 16);
        }
    };

    int t = blockIdx.x;
    if (t >= n_tiles) return;

    const __nv_bfloat16 *curA, *curB, *nxtA, *nxtB;
    __nv_bfloat16 *curC, *nxtC;
    size_t curM, nxtM;
    int curN, nxtN;
    decode(t, curA, curB, curC, curM, curN);

    load_chunk(curA, curB, curM, curN, 0, 0); __pipeline_commit();
    load_chunk(curA, curB, curM, curN, 1, 1); __pipeline_commit();

    int buf_c = 0;   // buffer of chunk being computed
    int buf_l = 2;   // buffer of chunk being loaded (2 ahead)

    float acc[4][8][4];
#pragma unroll
    for (int i = 0; i < 4; i++)
#pragma unroll
        for (int j = 0; j < 8; j++)
#pragma unroll
            for (int e = 0; e < 4; e++) acc[i][j][e] = 0.f;

    uint32_t a[2][4][4], b[2][4][4];

    while (true) {
        int t2 = t + stride;
        bool hn = (t2 < n_tiles);
        if (hn) decode(t2, nxtA, nxtB, nxtC, nxtM, nxtN);

        for (int kt = 0; kt < NT_K; kt++) {
            __pipeline_wait_prior(1);
            __syncthreads();

            if (kt < NT_K - 2)  load_chunk(curA, curB, curM, curN, kt + 2, buf_l);
            else if (hn)        load_chunk(nxtA, nxtB, nxtM, nxtN, kt + 2 - NT_K, buf_l);
            __pipeline_commit();

            uint32_t st = sm0_u + (uint32_t)(buf_c * STAGE_BYTES);

#pragma unroll
            for (int mi = 0; mi < 4; mi++) ldsm_x4(a[0][mi], st + offA[mi]);
#pragma unroll
            for (int pi = 0; pi < 4; pi++) ldsm_x4(b[0][pi], st + offB[pi]);

#pragma unroll
            for (int cs = 0; cs < 4; cs++) {
                int cur = cs & 1, nxt = cur ^ 1;
                if (cs < 3) {
                    uint32_t koff = (uint32_t)((cs + 1) * 32);
#pragma unroll
                    for (int mi = 0; mi < 4; mi++) ldsm_x4(a[nxt][mi], st + offA[mi] + koff);
#pragma unroll
                    for (int pi = 0; pi < 4; pi++) ldsm_x4(b[nxt][pi], st + offB[pi] + koff);
                }
#pragma unroll
                for (int mi = 0; mi < 4; mi++)
#pragma unroll
                    for (int ni = 0; ni < 8; ni++) {
                        int pi = ni >> 1, sel = (ni & 1) * 2;
                        mma16816(acc[mi][ni], a[cur][mi], b[cur][pi][sel], b[cur][pi][sel + 1]);
                    }
            }

            buf_c = (buf_c == 2) ? 0 : buf_c + 1;
            buf_l = (buf_l == 2) ? 0 : buf_l + 1;
        }

        // ---- epilogue: stage into the just-freed buffer (last computed chunk) ----
        int fb = (buf_c == 0) ? 2 : buf_c - 1;
        __syncthreads();   // all warps done reading buffer fb
        float* stage = reinterpret_cast<float*>(sm0 + fb * STAGE_BYTES) + wid * 1088;

        int srow = lane >> 2;
        int scol0 = (lane & 3) * 2;

#pragma unroll
        for (int mi = 0; mi < 4; mi++) {
#pragma unroll
            for (int ni = 0; ni < 8; ni++) {
                int col = ni * 8 + scol0;
                stage[srow * EPIPITCH + col]           = acc[mi][ni][0];
                stage[srow * EPIPITCH + col + 1]       = acc[mi][ni][1];
                stage[(srow + 8) * EPIPITCH + col]     = acc[mi][ni][2];
                stage[(srow + 8) * EPIPITCH + col + 1] = acc[mi][ni][3];
            }
            __syncwarp();
            size_t grow = curM + wm + mi * 16;

            if (WHICH == 0) {
#pragma unroll
                for (int u = 0; u < 16; u++) {
                    int e = lane + u * 32;
                    int r = e >> 5, c2 = e & 31;
                    float2 f2 = *reinterpret_cast<const float2*>(stage + r * EPIPITCH + c2 * 2);
                    __nv_bfloat162 h2 = __floats2bfloat162_rn(f2.x, f2.y);
                    *reinterpret_cast<__nv_bfloat162*>(
                        curC + (grow + r) * D_MODEL + curN + wn + c2 * 2) = h2;
                }
            } else {
#pragma unroll
                for (int u = 0; u < 16; u++) {
                    int e = lane + u * 32;
                    int r = e >> 5, c2 = e & 31;
                    int gc = curN + wn + c2 * 2;
                    float2 f2 = *reinterpret_cast<const float2*>(stage + r * EPIPITCH + c2 * 2);
                    float2 b2 = *reinterpret_cast<const float2*>(bout + gc);
                    float2 ff = *reinterpret_cast<const float2*>(feat + (grow + r) * D_MODEL + gc);
                    float2 o2;
                    o2.x = f2.x + b2.x + ff.x;
                    o2.y = f2.y + b2.y + ff.y;
                    *reinterpret_cast<float2*>(outp + (grow + r) * D_MODEL + gc) = o2;
                }
            }
            __syncwarp();
        }

        if (!hn) break;
        t = t2;
        curA = nxtA; curB = nxtB; curC = nxtC; curM = nxtM; curN = nxtN;
#pragma unroll
        for (int i = 0; i < 4; i++)
#pragma unroll
            for (int j = 0; j < 8; j++)
#pragma unroll
                for (int e = 0; e < 4; e++) acc[i][j][e] = 0.f;
    }
}

// ---------------- attention: one warp per (n, h), L = 9, all bf16 ---------------
__global__ void __launch_bounds__(256) attn_kernel()
{
    int warp = (blockIdx.x * blockDim.x + threadIdx.x) >> 5;
    int lane = threadIdx.x & 31;
    int n = warp >> 4;
    int h = warp & 15;

    size_t qoff = (size_t)n * D_MODEL + h * DHEAD + lane * 2;
    __nv_bfloat162 q2 = *reinterpret_cast<const __nv_bfloat162*>(g_q_h + qoff);
    float2 q = __bfloat1622float2(q2);

    float sc[LCTX];
#pragma unroll
    for (int l = 0; l < LCTX; l++) {
        size_t koff = (size_t)(n * LCTX + l) * D_MODEL + h * DHEAD + lane * 2;
        __nv_bfloat162 k2 = *reinterpret_cast<const __nv_bfloat162*>(g_k_h + koff);
        float2 kk = __bfloat1622float2(k2);
        float p = q.x * kk.x + q.y * kk.y;
#pragma unroll
        for (int o = 16; o; o >>= 1) p += __shfl_xor_sync(0xFFFFFFFFu, p, o);
        sc[l] = p * 0.125f;
    }
    float m = sc[0];
#pragma unroll
    for (int l = 1; l < LCTX; l++) m = fmaxf(m, sc[l]);
    float sum = 0.f;
#pragma unroll
    for (int l = 0; l < LCTX; l++) { sc[l] = __expf(sc[l] - m); sum += sc[l]; }
    float inv = 1.f / sum;

    float ox = 0.f, oy = 0.f;
#pragma unroll
    for (int l = 0; l < LCTX; l++) {
        size_t voff = (size_t)(n * LCTX + l) * D_MODEL + h * DHEAD + lane * 2;
        __nv_bfloat162 v2 = *reinterpret_cast<const __nv_bfloat162*>(g_v_h + voff);
        float2 vv = __bfloat1622float2(v2);
        float p = sc[l] * inv;
        ox = fmaf(p, vv.x, ox);
        oy = fmaf(p, vv.y, oy);
    }
    __nv_bfloat162 o2 = __floats2bfloat162_rn(ox, oy);
    *reinterpret_cast<__nv_bfloat162*>(g_o_h + qoff) = o2;
}

// ---------------- launch ----------------
extern "C" void kernel_launch(void* const* d_in, const int* in_sizes, int n_in,
                              void* d_out, int out_size)
{
    const float* feat = (const float*)d_in[0];
    const float* ctx  = (const float*)d_in[1];
    const float* qg   = (const float*)d_in[2];
    const float* qb   = (const float*)d_in[3];
    const float* cg   = (const float*)d_in[4];
    const float* cb   = (const float*)d_in[5];
    const float* Wq   = (const float*)d_in[6];
    const float* Wk   = (const float*)d_in[7];
    const float* Wv   = (const float*)d_in[8];
    const float* Wout = (const float*)d_in[9];
    const float* bout = (const float*)d_in[10];
    float* out = (float*)d_out;

    int nsm = 148;
    cudaDeviceGetAttribute(&nsm, cudaDevAttrMultiProcessorCount, 0);
    int grid = nsm * 2;

    cudaFuncSetAttribute(gemm_pers<0>, cudaFuncAttributeMaxDynamicSharedMemorySize, GEMM_SMEM_DYN);
    cudaFuncSetAttribute(gemm_pers<1>, cudaFuncAttributeMaxDynamicSharedMemorySize, GEMM_SMEM_DYN);

    cvtT_kernel<0><<<dim3(32, 32), 256>>>(Wq);
    cvtT_kernel<1><<<dim3(32, 32), 256>>>(Wk);
    cvtT_kernel<2><<<dim3(32, 32), 256>>>(Wv);
    cvtT_kernel<3><<<dim3(32, 32), 256>>>(Wout);

    // warps: N_SEQ dual-output + N_SEQ*8 context = 294912 warps / 8 per block
    ln_kernel<<<MROWS_C / 8, 256>>>(feat, ctx, qg, qb, cg, cb);

    gemm_pers<0><<<grid, 128, GEMM_SMEM_DYN>>>(QKV_TILES, nullptr, nullptr, nullptr);

    attn_kernel<<<(N_SEQ * HEADS) / 8, 256>>>();

    gemm_pers<1><<<grid, 128, GEMM_SMEM_DYN>>>(OUT_TILES, feat, bout, out);
}